// round 2
// baseline (speedup 1.0000x reference)
#include <cuda_runtime.h>
#include <cuda_bf16.h>
#include <math_constants.h>

#define NM 1024
#define HH 256
#define WW 256
#define HW (HH * WW)

// Scratch (no cudaMalloc allowed)
__device__ int   g_hi[NM];
__device__ int   g_lo[NM];
__device__ int   g_rmin[NM];
__device__ int   g_rmax[NM];
__device__ int   g_cmin[NM];
__device__ int   g_cmax[NM];
__device__ float g_gated[NM];

// ---------------------------------------------------------------------------
// Kernel A: per-mask stats. One block per mask, 256 threads.
// Thread layout: tx = tid&63 owns columns [4*tx, 4*tx+3] (float4 coalesced),
// ty = tid>>6 owns row stripe [64*ty, 64*ty+63].
// Per-thread trackers of row/col min/max where logit>0 reduce to the bbox.
// ---------------------------------------------------------------------------
__global__ void __launch_bounds__(256) stats_kernel(const float* __restrict__ logits) {
    const int n  = blockIdx.x;
    const int tid = threadIdx.x;
    const int tx = tid & 63;
    const int ty = tid >> 6;
    const int col0 = tx * 4;

    const float4* __restrict__ base =
        reinterpret_cast<const float4*>(logits + (size_t)n * HW);

    int hi = 0, lo = 0;
    int rmin = HH, rmax = -1, cmin = WW, cmax = -1;

    const int r0 = ty * 64;
#pragma unroll 4
    for (int rr = 0; rr < 64; rr++) {
        const int r = r0 + rr;
        float4 v = base[r * (WW / 4) + tx];
        hi += (v.x > 1.f) + (v.y > 1.f) + (v.z > 1.f) + (v.w > 1.f);
        lo += (v.x > -1.f) + (v.y > -1.f) + (v.z > -1.f) + (v.w > -1.f);
        int m = (v.x > 0.f) | ((v.y > 0.f) << 1) | ((v.z > 0.f) << 2) | ((v.w > 0.f) << 3);
        if (m) {
            rmin = min(rmin, r);
            rmax = max(rmax, r);
            cmin = min(cmin, col0 + (__ffs(m) - 1));
            cmax = max(cmax, col0 + (31 - __clz(m)));
        }
    }

    // warp reduce
#pragma unroll
    for (int o = 16; o > 0; o >>= 1) {
        hi   += __shfl_down_sync(0xffffffffu, hi, o);
        lo   += __shfl_down_sync(0xffffffffu, lo, o);
        rmin  = min(rmin, __shfl_down_sync(0xffffffffu, rmin, o));
        rmax  = max(rmax, __shfl_down_sync(0xffffffffu, rmax, o));
        cmin  = min(cmin, __shfl_down_sync(0xffffffffu, cmin, o));
        cmax  = max(cmax, __shfl_down_sync(0xffffffffu, cmax, o));
    }

    __shared__ int s_hi, s_lo, s_rmin, s_rmax, s_cmin, s_cmax;
    if (tid == 0) { s_hi = 0; s_lo = 0; s_rmin = HH; s_rmax = -1; s_cmin = WW; s_cmax = -1; }
    __syncthreads();
    if ((tid & 31) == 0) {
        atomicAdd(&s_hi, hi);
        atomicAdd(&s_lo, lo);
        atomicMin(&s_rmin, rmin);
        atomicMax(&s_rmax, rmax);
        atomicMin(&s_cmin, cmin);
        atomicMax(&s_cmax, cmax);
    }
    __syncthreads();
    if (tid == 0) {
        g_hi[n]   = s_hi;
        g_lo[n]   = s_lo;
        g_rmin[n] = s_rmin;
        g_rmax[n] = s_rmax;
        g_cmin[n] = s_cmin;
        g_cmax[n] = s_cmax;
    }
}

// ---------------------------------------------------------------------------
// Kernel B: single block (1024 threads). Build boxes + validity, bitonic sort
// by score (desc, stable via index tie-break), greedy NMS over V valid entries,
// write keep/boxes/gated.
// ---------------------------------------------------------------------------
__global__ void __launch_bounds__(1024) nms_kernel(const float* __restrict__ iou,
                                                   float* __restrict__ out_keep,
                                                   float* __restrict__ out_boxes,
                                                   int write_extra) {
    __shared__ float s_score[NM];
    __shared__ int   s_idx[NM];
    __shared__ float s_b0[NM], s_b1[NM], s_b2[NM], s_b3[NM];
    __shared__ unsigned char s_keep[NM];
    __shared__ int s_V;

    const int tid = threadIdx.x;

    // Box (original-index order)
    int rmax = g_rmax[tid];
    float b0, b1, b2, b3;
    if (rmax < 0) {
        b0 = b1 = b2 = b3 = 0.f;  // empty mask -> zeros (matches reference)
    } else {
        b0 = (float)g_cmin[tid];
        b1 = (float)g_rmin[tid];
        b2 = (float)g_cmax[tid];
        b3 = (float)rmax;
    }
    s_b0[tid] = b0; s_b1[tid] = b1; s_b2[tid] = b2; s_b3[tid] = b3;

    float ip   = iou[tid];
    float stab = (float)g_hi[tid] / fmaxf((float)g_lo[tid], 1.0f);
    bool valid = (ip > 0.88f) && (stab >= 0.95f);

    s_score[tid] = valid ? ip : -CUDART_INF_F;
    s_idx[tid]   = tid;
    if (tid == 0) s_V = NM;
    __syncthreads();

    // Bitonic sort, descending by score, index-ascending tie-break (stable equiv.)
    for (int k = 2; k <= NM; k <<= 1) {
        for (int j = k >> 1; j > 0; j >>= 1) {
            int ixj = tid ^ j;
            if (ixj > tid) {
                float sa = s_score[tid], sb = s_score[ixj];
                int   ia = s_idx[tid],   ib = s_idx[ixj];
                bool dir = ((tid & k) == 0);            // descending segment
                bool aBb = (sa > sb) || (sa == sb && ia < ib);
                bool bBa = (sb > sa) || (sb == sa && ib < ia);
                bool sw  = dir ? bBa : aBb;
                if (sw) {
                    s_score[tid] = sb; s_score[ixj] = sa;
                    s_idx[tid]   = ib; s_idx[ixj]   = ia;
                }
            }
            __syncthreads();
        }
    }

    const int oi = s_idx[tid];
    bool alive = (s_score[tid] != -CUDART_INF_F);
    s_keep[tid] = alive ? 1 : 0;
    if (!alive) atomicMin(&s_V, tid);
    __syncthreads();
    const int V = s_V;

    const float mb0 = s_b0[oi], mb1 = s_b1[oi], mb2 = s_b2[oi], mb3 = s_b3[oi];
    const float myArea = fmaxf(mb2 - mb0, 0.f) * fmaxf(mb3 - mb1, 0.f);

    for (int i = 0; i < V; i++) {
        if (s_keep[i] && tid > i && s_keep[tid]) {
            int pi = s_idx[i];
            float p0 = s_b0[pi], p1 = s_b1[pi], p2 = s_b2[pi], p3 = s_b3[pi];
            float x0 = fmaxf(p0, mb0), y0 = fmaxf(p1, mb1);
            float x1 = fminf(p2, mb2), y1 = fminf(p3, mb3);
            float inter = fmaxf(x1 - x0, 0.f) * fmaxf(y1 - y0, 0.f);
            float pa = fmaxf(p2 - p0, 0.f) * fmaxf(p3 - p1, 0.f);
            float v  = inter / fmaxf(pa + myArea - inter, 1e-6f);
            if (v > 0.7f) s_keep[tid] = 0;
        }
        __syncthreads();
    }

    bool kept = (s_keep[tid] != 0);
    g_gated[oi] = kept ? iou[oi] : 0.f;
    if (write_extra) {
        out_keep[oi] = kept ? 1.f : 0.f;
        float4 bx = make_float4(s_b0[oi], s_b1[oi], s_b2[oi], s_b3[oi]);
        reinterpret_cast<float4*>(out_boxes)[oi] = bx;
    }
}

// ---------------------------------------------------------------------------
// Kernel C: out = sigmoid(logits) * gated[n]. Blocks covering zero-gated
// masks skip the load and stream zeros (saves ~90% of the read traffic).
// grid = (16, NM), 256 threads, 4 coalesced float4 per thread.
// ---------------------------------------------------------------------------
__global__ void __launch_bounds__(256) out_kernel(const float* __restrict__ logits,
                                                  float* __restrict__ out) {
    const int n   = blockIdx.y;
    const int tid = threadIdx.x;
    const size_t base = (size_t)n * HW + (size_t)blockIdx.x * 4096;
    const float4* __restrict__ in4 = reinterpret_cast<const float4*>(logits + base);
    float4* __restrict__ o4 = reinterpret_cast<float4*>(out + base);

    const float g = g_gated[n];
    if (g == 0.f) {
        const float4 z = make_float4(0.f, 0.f, 0.f, 0.f);
#pragma unroll
        for (int k = 0; k < 4; k++) o4[k * 256 + tid] = z;
    } else {
#pragma unroll
        for (int k = 0; k < 4; k++) {
            float4 v = in4[k * 256 + tid];
            float4 r;
            r.x = g / (1.f + __expf(-v.x));
            r.y = g / (1.f + __expf(-v.y));
            r.z = g / (1.f + __expf(-v.z));
            r.w = g / (1.f + __expf(-v.w));
            o4[k * 256 + tid] = r;
        }
    }
}

// ---------------------------------------------------------------------------
extern "C" void kernel_launch(void* const* d_in, const int* in_sizes, int n_in,
                              void* d_out, int out_size) {
    const float* logits = (const float*)d_in[0];
    const float* iou    = (const float*)d_in[1];
    // Defensive: detect input ordering by element count.
    if (n_in >= 2 && in_sizes[0] == NM && in_sizes[1] == NM * HW) {
        logits = (const float*)d_in[1];
        iou    = (const float*)d_in[0];
    }

    float* out = (float*)d_out;
    const long long NHW = (long long)NM * HW;
    int write_extra = (out_size >= NHW + NM + NM * 4) ? 1 : 0;
    float* out_keep  = out + NHW;
    float* out_boxes = out + NHW + NM;

    stats_kernel<<<NM, 256>>>(logits);
    nms_kernel<<<1, 1024>>>(iou, out_keep, out_boxes, write_extra);
    out_kernel<<<dim3(16, NM), 256>>>(logits, out);
}